// round 15
// baseline (speedup 1.0000x reference)
#include <cuda_runtime.h>
#include <cstdint>

#define MC    32                     // matrices per micro-chunk (= warp size)
#define MCF   (MC * 81)              // 2592 floats
#define MCB   (MC * 81 * 4)          // 10368 bytes
#define DEPTH 3
#define SMEM_DYN (DEPTH * MCB)       // 31104 B -> 7 one-warp blocks/SM

__device__ __forceinline__ unsigned s2u(const void* p) {
    return (unsigned)__cvta_generic_to_shared(p);
}
__device__ __forceinline__ void mbar_init(unsigned mb, unsigned count) {
    asm volatile("mbarrier.init.shared.b64 [%0], %1;" :: "r"(mb), "r"(count) : "memory");
}
__device__ __forceinline__ void mbar_wait(unsigned mb, unsigned phase) {
    asm volatile(
        "{\n\t"
        ".reg .pred P;\n\t"
        "LW_%=:\n\t"
        "mbarrier.try_wait.parity.acquire.cta.shared::cta.b64 P, [%0], %1, 0x989680;\n\t"
        "@P bra LD_%=;\n\t"
        "bra LW_%=;\n\t"
        "LD_%=:\n\t"
        "}"
        :: "r"(mb), "r"(phase) : "memory");
}
__device__ __forceinline__ void issue_bulk(unsigned sdst, const float* gsrc,
                                           unsigned bytes, unsigned mb) {
    asm volatile("fence.proxy.async.shared::cta;" ::: "memory");
    asm volatile("mbarrier.arrive.expect_tx.shared.b64 _, [%0], %1;"
                 :: "r"(mb), "r"(bytes) : "memory");
    asm volatile(
        "cp.async.bulk.shared::cta.global.mbarrier::complete_tx::bytes [%0], [%1], %2, [%3];"
        :: "r"(sdst), "l"(gsrc), "r"(bytes), "r"(mb) : "memory");
}

// Full per-matrix pipeline: C = Wc^T X Wc (3x3 sym), then logm(C) vech.
// Epilogue built on parallel __logf's: short serial chains, few divides.
__device__ __forceinline__ void compute_store(const float* __restrict__ m,
                                              const float* __restrict__ sW,
                                              float* __restrict__ outp) {
    float c00 = 0.f, c01 = 0.f, c02 = 0.f, c11 = 0.f, c12 = 0.f, c22 = 0.f;
    #pragma unroll
    for (int i = 0; i < 9; ++i) {
        float u0 = 0.f, u1 = 0.f, u2 = 0.f;
        #pragma unroll
        for (int j = 0; j < 9; ++j) {
            float xv = m[i * 9 + j];
            u0 = fmaf(xv, sW[j * 3 + 0], u0);
            u1 = fmaf(xv, sW[j * 3 + 1], u1);
            u2 = fmaf(xv, sW[j * 3 + 2], u2);
        }
        float w0 = sW[i * 3 + 0], w1 = sW[i * 3 + 1], w2 = sW[i * 3 + 2];
        c00 = fmaf(w0, u0, c00);
        c01 = fmaf(w0, u1, c01);
        c02 = fmaf(w0, u2, c02);
        c11 = fmaf(w1, u1, c11);
        c12 = fmaf(w1, u2, c12);
        c22 = fmaf(w2, u2, c22);
    }

    // ---- 3x3 symmetric eigenvalues (trig closed form) ----
    float q = (c00 + c11 + c22) * (1.0f / 3.0f);
    float b00 = c00 - q, b11 = c11 - q, b22 = c22 - q;
    float p2 = b00 * b00 + b11 * b11 + b22 * b22 +
               2.0f * (c01 * c01 + c02 * c02 + c12 * c12);
    float p2s = fmaxf(p2 * (1.0f / 6.0f), 1e-30f);
    float rs = rsqrtf(p2s);
    float p = p2s * rs;                 // sqrt(p2s)
    float pinv = rs;                    // 1/sqrt(p2s) == 1/p (no divide)

    float d00 = b00 * pinv, d11 = b11 * pinv, d22 = b22 * pinv;
    float e01 = c01 * pinv, e02 = c02 * pinv, e12 = c12 * pinv;
    float detB = d00 * (d11 * d22 - e12 * e12)
               - e01 * (e01 * d22 - e12 * e02)
               + e02 * (e01 * e12 - d11 * e02);
    float r = 0.5f * detB;
    r = fmaxf(-1.0f, fminf(1.0f, r));
    float phi = acosf(r) * (1.0f / 3.0f);
    float sph = __sinf(phi);
    float cph = __cosf(phi);
    float l1 = q + 2.0f * p * cph;
    float l3 = q + p * (-cph - 1.7320508075688772f * sph);
    float l2 = 3.0f * q - l1 - l3;

    l3 = fmaxf(l3, 1e-8f);
    l2 = fmaxf(l2, l3);
    l1 = fmaxf(l1, l2);

    // ---- logs of eigenvalues: 3 independent chains (overlap with FMAs below) ----
    float L1 = __logf(l1);
    float L2 = __logf(l2);
    float L3 = __logf(l3);

    float g32 = l2 - l3, g21 = l1 - l2, g31 = l1 - l3;
    float s32 = l2 + l3, s21 = l1 + l2, s31 = l1 + l3;

    // divided differences from precomputed logs; series fallback on tiny gaps
    float f32, f21;
    if (g32 > 0.02f * s32) {
        f32 = __fdividef(L2 - L3, g32);
    } else {
        float h = __fdividef(2.0f, s32);
        float w = 0.5f * g32 * h;
        f32 = h * fmaf(w * w, 0.33333333f, 1.0f);
    }
    if (g21 > 0.02f * s21) {
        f21 = __fdividef(L1 - L2, g21);
    } else {
        float h = __fdividef(2.0f, s21);
        float w = 0.5f * g21 * h;
        f21 = h * fmaf(w * w, 0.33333333f, 1.0f);
    }
    float d2v;
    if (g31 > 5e-4f * s31) {
        d2v = __fdividef(f21 - f32, g31);
    } else {
        float h = __fdividef(2.0f, s31);
        d2v = -0.5f * h * h;
    }
    float d0v = L3;
    float d1v = f32;

    float m00 = c00 - l3, m11 = c11 - l3, m22 = c22 - l3;
    float n00 = c00 - l2, n11 = c11 - l2, n22 = c22 - l2;
    float p00 = m00 * n00 + c01 * c01 + c02 * c02;
    float p01 = m00 * c01 + c01 * n11 + c02 * c12;
    float p02 = m00 * c02 + c01 * c12 + c02 * n22;
    float p11 = c01 * c01 + m11 * n11 + c12 * c12;
    float p12 = c01 * c02 + m11 * c12 + c12 * n22;
    float p22 = c02 * c02 + c12 * c12 + m22 * n22;

    float2 r01, r23, r45;
    r01.x = fmaf(d2v, p00, fmaf(d1v, m00, d0v));
    r01.y = fmaf(d2v, p01, d1v * c01);
    r23.x = fmaf(d2v, p02, d1v * c02);
    r23.y = fmaf(d2v, p11, fmaf(d1v, m11, d0v));
    r45.x = fmaf(d2v, p12, d1v * c12);
    r45.y = fmaf(d2v, p22, fmaf(d1v, m22, d0v));

    float2* ob = reinterpret_cast<float2*>(outp);
    ob[0] = r01;
    ob[1] = r23;
    ob[2] = r45;
}

__global__ __launch_bounds__(32, 7) void spd_kernel(const float* __restrict__ X,
                                                    const float* __restrict__ W1,
                                                    const float* __restrict__ W2,
                                                    const float* __restrict__ W3,
                                                    float* __restrict__ out,
                                                    int B, int nmc) {
    extern __shared__ __align__(16) float dsm[];           // DEPTH x 2592 floats
    __shared__ __align__(8) unsigned long long mbar_s[DEPTH];
    __shared__ float sW[27];

    const int lane = threadIdx.x;

    // Wc = W1 @ W2 @ W3 (9x3); tiny, L2-resident across blocks
    if (lane < 27) {
        int i = lane / 3, cc = lane % 3;
        float s = 0.f;
        #pragma unroll
        for (int m5 = 0; m5 < 5; ++m5) {
            float t = 0.f;
            #pragma unroll
            for (int k = 0; k < 7; ++k)
                t = fmaf(__ldg(W1 + i * 7 + k), __ldg(W2 + k * 5 + m5), t);
            s = fmaf(t, __ldg(W3 + m5 * 3 + cc), s);
        }
        sW[lane] = s;
    }

    const unsigned mb0 = s2u(&mbar_s[0]);
    const unsigned mb1 = s2u(&mbar_s[1]);
    const unsigned mb2 = s2u(&mbar_s[2]);
    if (lane == 0) {
        mbar_init(mb0, 1);
        mbar_init(mb1, 1);
        mbar_init(mb2, 1);
    }
    __syncwarp();   // mbarrier init + sW visible warp-wide

    unsigned ph0 = 0, ph1 = 0, ph2 = 0;
    const unsigned sb0 = s2u(dsm);
    const unsigned sb1 = sb0 + MCB;
    const unsigned sb2 = sb0 + 2 * MCB;
    const float* d0 = dsm;
    const float* d1 = dsm + MCF;
    const float* d2 = dsm + 2 * MCF;

    const int c0 = blockIdx.x;
    const int stride = gridDim.x;

    // prologue: fill slots 0 and 1 (prefetch distance 2)
    if (lane == 0) {
        if (c0 < nmc && (c0 + 1) * MC <= B)
            issue_bulk(sb0, X + (size_t)c0 * MCF, MCB, mb0);
        int cp = c0 + stride;
        if (cp < nmc && (cp + 1) * MC <= B)
            issue_bulk(sb1, X + (size_t)cp * MCF, MCB, mb1);
    }

    for (int c = c0; c < nmc; c += 3 * stride) {
        // ---- slot 0: chunk c ----
        {
            int pn = c + 2 * stride;     // prefetch into slot 2
            if (pn < nmc && (pn + 1) * MC <= B && lane == 0)
                issue_bulk(sb2, X + (size_t)pn * MCF, MCB, mb2);
            int bstart = c * MC;
            if (bstart + MC <= B) {
                mbar_wait(mb0, ph0); ph0 ^= 1;
                compute_store(d0 + lane * 81, sW, out + ((size_t)bstart + lane) * 6);
            } else if (bstart + lane < B) {
                float xl[81];
                const float* g = X + ((size_t)bstart + lane) * 81;
                #pragma unroll
                for (int e = 0; e < 81; ++e) xl[e] = __ldg(g + e);
                compute_store(xl, sW, out + ((size_t)bstart + lane) * 6);
            }
        }
        // ---- slot 1: chunk c + stride ----
        int c1 = c + stride;
        if (c1 < nmc) {
            int pn = c1 + 2 * stride;    // prefetch into slot 0
            if (pn < nmc && (pn + 1) * MC <= B && lane == 0)
                issue_bulk(sb0, X + (size_t)pn * MCF, MCB, mb0);
            int bstart = c1 * MC;
            if (bstart + MC <= B) {
                mbar_wait(mb1, ph1); ph1 ^= 1;
                compute_store(d1 + lane * 81, sW, out + ((size_t)bstart + lane) * 6);
            } else if (bstart + lane < B) {
                float xl[81];
                const float* g = X + ((size_t)bstart + lane) * 81;
                #pragma unroll
                for (int e = 0; e < 81; ++e) xl[e] = __ldg(g + e);
                compute_store(xl, sW, out + ((size_t)bstart + lane) * 6);
            }
        }
        // ---- slot 2: chunk c + 2*stride ----
        int c2 = c + 2 * stride;
        if (c2 < nmc) {
            int pn = c2 + 2 * stride;    // prefetch into slot 1
            if (pn < nmc && (pn + 1) * MC <= B && lane == 0)
                issue_bulk(sb1, X + (size_t)pn * MCF, MCB, mb1);
            int bstart = c2 * MC;
            if (bstart + MC <= B) {
                mbar_wait(mb2, ph2); ph2 ^= 1;
                compute_store(d2 + lane * 81, sW, out + ((size_t)bstart + lane) * 6);
            } else if (bstart + lane < B) {
                float xl[81];
                const float* g = X + ((size_t)bstart + lane) * 81;
                #pragma unroll
                for (int e = 0; e < 81; ++e) xl[e] = __ldg(g + e);
                compute_store(xl, sW, out + ((size_t)bstart + lane) * 6);
            }
        }
    }
}

extern "C" void kernel_launch(void* const* d_in, const int* in_sizes, int n_in,
                              void* d_out, int out_size) {
    const float* X  = (const float*)d_in[0];
    const float* W1 = (const float*)d_in[1];
    const float* W2 = (const float*)d_in[2];
    const float* W3 = (const float*)d_in[3];
    float* out = (float*)d_out;

    int B = in_sizes[0] / 81;
    int nmc = (B + MC - 1) / MC;

    int sms = 148;
    cudaDeviceGetAttribute(&sms, cudaDevAttrMultiProcessorCount, 0);
    int grid = 7 * sms;              // 7 one-warp blocks/SM (31.1 KB smem each)
    if (grid > nmc) grid = nmc;

    spd_kernel<<<grid, 32, SMEM_DYN>>>(X, W1, W2, W3, out, B, nmc);
}

// round 16
// speedup vs baseline: 1.0444x; 1.0444x over previous
#include <cuda_runtime.h>
#include <cstdint>

#define MC    32                     // matrices per micro-chunk (= warp size)
#define MCF   (MC * 81)              // 2592 floats
#define MCB   (MC * 81 * 4)          // 10368 bytes
#define DEPTH 3
#define SMEM_DYN (DEPTH * MCB)       // 31104 B -> 7 one-warp blocks/SM

__device__ __forceinline__ unsigned s2u(const void* p) {
    return (unsigned)__cvta_generic_to_shared(p);
}
__device__ __forceinline__ void mbar_init(unsigned mb, unsigned count) {
    asm volatile("mbarrier.init.shared.b64 [%0], %1;" :: "r"(mb), "r"(count) : "memory");
}
__device__ __forceinline__ void mbar_wait(unsigned mb, unsigned phase) {
    asm volatile(
        "{\n\t"
        ".reg .pred P;\n\t"
        "LW_%=:\n\t"
        "mbarrier.try_wait.parity.acquire.cta.shared::cta.b64 P, [%0], %1, 0x989680;\n\t"
        "@P bra LD_%=;\n\t"
        "bra LW_%=;\n\t"
        "LD_%=:\n\t"
        "}"
        :: "r"(mb), "r"(phase) : "memory");
}
__device__ __forceinline__ void issue_bulk(unsigned sdst, const float* gsrc,
                                           unsigned bytes, unsigned mb) {
    asm volatile("fence.proxy.async.shared::cta;" ::: "memory");
    asm volatile("mbarrier.arrive.expect_tx.shared.b64 _, [%0], %1;"
                 :: "r"(mb), "r"(bytes) : "memory");
    asm volatile(
        "cp.async.bulk.shared::cta.global.mbarrier::complete_tx::bytes [%0], [%1], %2, [%3];"
        :: "r"(sdst), "l"(gsrc), "r"(bytes), "r"(mb) : "memory");
}

// Full per-matrix pipeline: C = Wc^T X Wc (3x3 sym), then logm(C) vech.
// Epilogue built on parallel __logf's: short serial chains, few divides.
__device__ __forceinline__ void compute_store(const float* __restrict__ m,
                                              const float* __restrict__ sW,
                                              float* __restrict__ outp) {
    float c00 = 0.f, c01 = 0.f, c02 = 0.f, c11 = 0.f, c12 = 0.f, c22 = 0.f;
    #pragma unroll
    for (int i = 0; i < 9; ++i) {
        float u0 = 0.f, u1 = 0.f, u2 = 0.f;
        #pragma unroll
        for (int j = 0; j < 9; ++j) {
            float xv = m[i * 9 + j];
            u0 = fmaf(xv, sW[j * 3 + 0], u0);
            u1 = fmaf(xv, sW[j * 3 + 1], u1);
            u2 = fmaf(xv, sW[j * 3 + 2], u2);
        }
        float w0 = sW[i * 3 + 0], w1 = sW[i * 3 + 1], w2 = sW[i * 3 + 2];
        c00 = fmaf(w0, u0, c00);
        c01 = fmaf(w0, u1, c01);
        c02 = fmaf(w0, u2, c02);
        c11 = fmaf(w1, u1, c11);
        c12 = fmaf(w1, u2, c12);
        c22 = fmaf(w2, u2, c22);
    }

    // ---- 3x3 symmetric eigenvalues (trig closed form) ----
    float q = (c00 + c11 + c22) * (1.0f / 3.0f);
    float b00 = c00 - q, b11 = c11 - q, b22 = c22 - q;
    float p2 = b00 * b00 + b11 * b11 + b22 * b22 +
               2.0f * (c01 * c01 + c02 * c02 + c12 * c12);
    float p2s = fmaxf(p2 * (1.0f / 6.0f), 1e-30f);
    float rs = rsqrtf(p2s);
    float p = p2s * rs;                 // sqrt(p2s)
    float pinv = rs;                    // 1/sqrt(p2s) == 1/p (no divide)

    float d00 = b00 * pinv, d11 = b11 * pinv, d22 = b22 * pinv;
    float e01 = c01 * pinv, e02 = c02 * pinv, e12 = c12 * pinv;
    float detB = d00 * (d11 * d22 - e12 * e12)
               - e01 * (e01 * d22 - e12 * e02)
               + e02 * (e01 * e12 - d11 * e02);
    float r = 0.5f * detB;
    r = fmaxf(-1.0f, fminf(1.0f, r));
    float phi = acosf(r) * (1.0f / 3.0f);
    float sph = __sinf(phi);
    float cph = __cosf(phi);
    float l1 = q + 2.0f * p * cph;
    float l3 = q + p * (-cph - 1.7320508075688772f * sph);
    float l2 = 3.0f * q - l1 - l3;

    l3 = fmaxf(l3, 1e-8f);
    l2 = fmaxf(l2, l3);
    l1 = fmaxf(l1, l2);

    // ---- logs of eigenvalues: 3 independent chains (overlap with FMAs below) ----
    float L1 = __logf(l1);
    float L2 = __logf(l2);
    float L3 = __logf(l3);

    float g32 = l2 - l3, g21 = l1 - l2, g31 = l1 - l3;
    float s32 = l2 + l3, s21 = l1 + l2, s31 = l1 + l3;

    // divided differences from precomputed logs; series fallback on tiny gaps
    float f32, f21;
    if (g32 > 0.02f * s32) {
        f32 = __fdividef(L2 - L3, g32);
    } else {
        float h = __fdividef(2.0f, s32);
        float w = 0.5f * g32 * h;
        f32 = h * fmaf(w * w, 0.33333333f, 1.0f);
    }
    if (g21 > 0.02f * s21) {
        f21 = __fdividef(L1 - L2, g21);
    } else {
        float h = __fdividef(2.0f, s21);
        float w = 0.5f * g21 * h;
        f21 = h * fmaf(w * w, 0.33333333f, 1.0f);
    }
    float d2v;
    if (g31 > 5e-4f * s31) {
        d2v = __fdividef(f21 - f32, g31);
    } else {
        float h = __fdividef(2.0f, s31);
        d2v = -0.5f * h * h;
    }
    float d0v = L3;
    float d1v = f32;

    float m00 = c00 - l3, m11 = c11 - l3, m22 = c22 - l3;
    float n00 = c00 - l2, n11 = c11 - l2, n22 = c22 - l2;
    float p00 = m00 * n00 + c01 * c01 + c02 * c02;
    float p01 = m00 * c01 + c01 * n11 + c02 * c12;
    float p02 = m00 * c02 + c01 * c12 + c02 * n22;
    float p11 = c01 * c01 + m11 * n11 + c12 * c12;
    float p12 = c01 * c02 + m11 * c12 + c12 * n22;
    float p22 = c02 * c02 + c12 * c12 + m22 * n22;

    float2 r01, r23, r45;
    r01.x = fmaf(d2v, p00, fmaf(d1v, m00, d0v));
    r01.y = fmaf(d2v, p01, d1v * c01);
    r23.x = fmaf(d2v, p02, d1v * c02);
    r23.y = fmaf(d2v, p11, fmaf(d1v, m11, d0v));
    r45.x = fmaf(d2v, p12, d1v * c12);
    r45.y = fmaf(d2v, p22, fmaf(d1v, m22, d0v));

    float2* ob = reinterpret_cast<float2*>(outp);
    ob[0] = r01;
    ob[1] = r23;
    ob[2] = r45;
}

__global__ __launch_bounds__(32, 7) void spd_kernel(const float* __restrict__ X,
                                                    const float* __restrict__ W1,
                                                    const float* __restrict__ W2,
                                                    const float* __restrict__ W3,
                                                    float* __restrict__ out,
                                                    int B, int nmc) {
    extern __shared__ __align__(16) float dsm[];           // DEPTH x 2592 floats
    __shared__ __align__(8) unsigned long long mbar_s[DEPTH];
    __shared__ float sW[27];

    const int lane = threadIdx.x;

    // Wc = W1 @ W2 @ W3 (9x3); tiny, L2-resident across blocks
    if (lane < 27) {
        int i = lane / 3, cc = lane % 3;
        float s = 0.f;
        #pragma unroll
        for (int m5 = 0; m5 < 5; ++m5) {
            float t = 0.f;
            #pragma unroll
            for (int k = 0; k < 7; ++k)
                t = fmaf(__ldg(W1 + i * 7 + k), __ldg(W2 + k * 5 + m5), t);
            s = fmaf(t, __ldg(W3 + m5 * 3 + cc), s);
        }
        sW[lane] = s;
    }

    const unsigned mb0 = s2u(&mbar_s[0]);
    const unsigned mb1 = s2u(&mbar_s[1]);
    const unsigned mb2 = s2u(&mbar_s[2]);
    if (lane == 0) {
        mbar_init(mb0, 1);
        mbar_init(mb1, 1);
        mbar_init(mb2, 1);
    }
    __syncwarp();   // mbarrier init + sW visible warp-wide

    unsigned ph0 = 0, ph1 = 0, ph2 = 0;
    const unsigned sb0 = s2u(dsm);
    const unsigned sb1 = sb0 + MCB;
    const unsigned sb2 = sb0 + 2 * MCB;
    const float* d0 = dsm;
    const float* d1 = dsm + MCF;
    const float* d2 = dsm + 2 * MCF;

    const int c0 = blockIdx.x;
    const int stride = gridDim.x;

    // prologue: fill slots 0 and 1 (prefetch distance 2)
    if (lane == 0) {
        if (c0 < nmc && (c0 + 1) * MC <= B)
            issue_bulk(sb0, X + (size_t)c0 * MCF, MCB, mb0);
        int cp = c0 + stride;
        if (cp < nmc && (cp + 1) * MC <= B)
            issue_bulk(sb1, X + (size_t)cp * MCF, MCB, mb1);
    }

    for (int c = c0; c < nmc; c += 3 * stride) {
        // ---- slot 0: chunk c ----
        {
            int pn = c + 2 * stride;     // prefetch into slot 2
            if (pn < nmc && (pn + 1) * MC <= B && lane == 0)
                issue_bulk(sb2, X + (size_t)pn * MCF, MCB, mb2);
            int bstart = c * MC;
            if (bstart + MC <= B) {
                mbar_wait(mb0, ph0); ph0 ^= 1;
                compute_store(d0 + lane * 81, sW, out + ((size_t)bstart + lane) * 6);
            } else if (bstart + lane < B) {
                float xl[81];
                const float* g = X + ((size_t)bstart + lane) * 81;
                #pragma unroll
                for (int e = 0; e < 81; ++e) xl[e] = __ldg(g + e);
                compute_store(xl, sW, out + ((size_t)bstart + lane) * 6);
            }
        }
        // ---- slot 1: chunk c + stride ----
        int c1 = c + stride;
        if (c1 < nmc) {
            int pn = c1 + 2 * stride;    // prefetch into slot 0
            if (pn < nmc && (pn + 1) * MC <= B && lane == 0)
                issue_bulk(sb0, X + (size_t)pn * MCF, MCB, mb0);
            int bstart = c1 * MC;
            if (bstart + MC <= B) {
                mbar_wait(mb1, ph1); ph1 ^= 1;
                compute_store(d1 + lane * 81, sW, out + ((size_t)bstart + lane) * 6);
            } else if (bstart + lane < B) {
                float xl[81];
                const float* g = X + ((size_t)bstart + lane) * 81;
                #pragma unroll
                for (int e = 0; e < 81; ++e) xl[e] = __ldg(g + e);
                compute_store(xl, sW, out + ((size_t)bstart + lane) * 6);
            }
        }
        // ---- slot 2: chunk c + 2*stride ----
        int c2 = c + 2 * stride;
        if (c2 < nmc) {
            int pn = c2 + 2 * stride;    // prefetch into slot 1
            if (pn < nmc && (pn + 1) * MC <= B && lane == 0)
                issue_bulk(sb1, X + (size_t)pn * MCF, MCB, mb1);
            int bstart = c2 * MC;
            if (bstart + MC <= B) {
                mbar_wait(mb2, ph2); ph2 ^= 1;
                compute_store(d2 + lane * 81, sW, out + ((size_t)bstart + lane) * 6);
            } else if (bstart + lane < B) {
                float xl[81];
                const float* g = X + ((size_t)bstart + lane) * 81;
                #pragma unroll
                for (int e = 0; e < 81; ++e) xl[e] = __ldg(g + e);
                compute_store(xl, sW, out + ((size_t)bstart + lane) * 6);
            }
        }
    }
}

extern "C" void kernel_launch(void* const* d_in, const int* in_sizes, int n_in,
                              void* d_out, int out_size) {
    const float* X  = (const float*)d_in[0];
    const float* W1 = (const float*)d_in[1];
    const float* W2 = (const float*)d_in[2];
    const float* W3 = (const float*)d_in[3];
    float* out = (float*)d_out;

    int B = in_sizes[0] / 81;
    int nmc = (B + MC - 1) / MC;

    int sms = 148;
    cudaDeviceGetAttribute(&sms, cudaDevAttrMultiProcessorCount, 0);
    int grid = 7 * sms;              // 7 one-warp blocks/SM (31.1 KB smem each)
    if (grid > nmc) grid = nmc;

    spd_kernel<<<grid, 32, SMEM_DYN>>>(X, W1, W2, W3, out, B, nmc);
}

// round 17
// speedup vs baseline: 1.0453x; 1.0009x over previous
#include <cuda_runtime.h>
#include <cstdint>

#define MC    32                     // matrices per micro-chunk (= warp size)
#define MCF   (MC * 81)              // 2592 floats
#define MCB   (MC * 81 * 4)          // 10368 bytes
#define DEPTH 3
#define SMEM_DYN (DEPTH * MCB)       // 31104 B -> 7 one-warp blocks/SM

__device__ __forceinline__ unsigned s2u(const void* p) {
    return (unsigned)__cvta_generic_to_shared(p);
}
__device__ __forceinline__ void mbar_init(unsigned mb, unsigned count) {
    asm volatile("mbarrier.init.shared.b64 [%0], %1;" :: "r"(mb), "r"(count) : "memory");
}
__device__ __forceinline__ void mbar_wait(unsigned mb, unsigned phase) {
    asm volatile(
        "{\n\t"
        ".reg .pred P;\n\t"
        "LW_%=:\n\t"
        "mbarrier.try_wait.parity.acquire.cta.shared::cta.b64 P, [%0], %1, 0x989680;\n\t"
        "@P bra LD_%=;\n\t"
        "bra LW_%=;\n\t"
        "LD_%=:\n\t"
        "}"
        :: "r"(mb), "r"(phase) : "memory");
}
__device__ __forceinline__ void issue_bulk(unsigned sdst, const float* gsrc,
                                           unsigned bytes, unsigned mb) {
    asm volatile("fence.proxy.async.shared::cta;" ::: "memory");
    asm volatile("mbarrier.arrive.expect_tx.shared.b64 _, [%0], %1;"
                 :: "r"(mb), "r"(bytes) : "memory");
    asm volatile(
        "cp.async.bulk.shared::cta.global.mbarrier::complete_tx::bytes [%0], [%1], %2, [%3];"
        :: "r"(sdst), "l"(gsrc), "r"(bytes), "r"(mb) : "memory");
}

// Full per-matrix pipeline: C = Wc^T X Wc (3x3 sym), then logm(C) vech.
// Epilogue built on parallel __logf's: short serial chains, few divides.
__device__ __forceinline__ void compute_store(const float* __restrict__ m,
                                              const float* __restrict__ sW,
                                              float* __restrict__ outp) {
    float c00 = 0.f, c01 = 0.f, c02 = 0.f, c11 = 0.f, c12 = 0.f, c22 = 0.f;
    #pragma unroll
    for (int i = 0; i < 9; ++i) {
        float u0 = 0.f, u1 = 0.f, u2 = 0.f;
        #pragma unroll
        for (int j = 0; j < 9; ++j) {
            float xv = m[i * 9 + j];
            u0 = fmaf(xv, sW[j * 3 + 0], u0);
            u1 = fmaf(xv, sW[j * 3 + 1], u1);
            u2 = fmaf(xv, sW[j * 3 + 2], u2);
        }
        float w0 = sW[i * 3 + 0], w1 = sW[i * 3 + 1], w2 = sW[i * 3 + 2];
        c00 = fmaf(w0, u0, c00);
        c01 = fmaf(w0, u1, c01);
        c02 = fmaf(w0, u2, c02);
        c11 = fmaf(w1, u1, c11);
        c12 = fmaf(w1, u2, c12);
        c22 = fmaf(w2, u2, c22);
    }

    // ---- 3x3 symmetric eigenvalues (trig closed form) ----
    float q = (c00 + c11 + c22) * (1.0f / 3.0f);
    float b00 = c00 - q, b11 = c11 - q, b22 = c22 - q;
    float p2 = b00 * b00 + b11 * b11 + b22 * b22 +
               2.0f * (c01 * c01 + c02 * c02 + c12 * c12);
    float p2s = fmaxf(p2 * (1.0f / 6.0f), 1e-30f);
    float rs = rsqrtf(p2s);
    float p = p2s * rs;                 // sqrt(p2s)
    float pinv = rs;                    // 1/sqrt(p2s) == 1/p (no divide)

    float d00 = b00 * pinv, d11 = b11 * pinv, d22 = b22 * pinv;
    float e01 = c01 * pinv, e02 = c02 * pinv, e12 = c12 * pinv;
    float detB = d00 * (d11 * d22 - e12 * e12)
               - e01 * (e01 * d22 - e12 * e02)
               + e02 * (e01 * e12 - d11 * e02);
    float r = 0.5f * detB;
    r = fmaxf(-1.0f, fminf(1.0f, r));
    float phi = acosf(r) * (1.0f / 3.0f);
    float sph = __sinf(phi);
    float cph = __cosf(phi);
    float l1 = q + 2.0f * p * cph;
    float l3 = q + p * (-cph - 1.7320508075688772f * sph);
    float l2 = 3.0f * q - l1 - l3;

    l3 = fmaxf(l3, 1e-8f);
    l2 = fmaxf(l2, l3);
    l1 = fmaxf(l1, l2);

    // ---- logs of eigenvalues: 3 independent chains (overlap with FMAs below) ----
    float L1 = __logf(l1);
    float L2 = __logf(l2);
    float L3 = __logf(l3);

    float g32 = l2 - l3, g21 = l1 - l2, g31 = l1 - l3;
    float s32 = l2 + l3, s21 = l1 + l2, s31 = l1 + l3;

    // divided differences from precomputed logs; series fallback on tiny gaps
    float f32, f21;
    if (g32 > 0.02f * s32) {
        f32 = __fdividef(L2 - L3, g32);
    } else {
        float h = __fdividef(2.0f, s32);
        float w = 0.5f * g32 * h;
        f32 = h * fmaf(w * w, 0.33333333f, 1.0f);
    }
    if (g21 > 0.02f * s21) {
        f21 = __fdividef(L1 - L2, g21);
    } else {
        float h = __fdividef(2.0f, s21);
        float w = 0.5f * g21 * h;
        f21 = h * fmaf(w * w, 0.33333333f, 1.0f);
    }
    float d2v;
    if (g31 > 5e-4f * s31) {
        d2v = __fdividef(f21 - f32, g31);
    } else {
        float h = __fdividef(2.0f, s31);
        d2v = -0.5f * h * h;
    }
    float d0v = L3;
    float d1v = f32;

    float m00 = c00 - l3, m11 = c11 - l3, m22 = c22 - l3;
    float n00 = c00 - l2, n11 = c11 - l2, n22 = c22 - l2;
    float p00 = m00 * n00 + c01 * c01 + c02 * c02;
    float p01 = m00 * c01 + c01 * n11 + c02 * c12;
    float p02 = m00 * c02 + c01 * c12 + c02 * n22;
    float p11 = c01 * c01 + m11 * n11 + c12 * c12;
    float p12 = c01 * c02 + m11 * c12 + c12 * n22;
    float p22 = c02 * c02 + c12 * c12 + m22 * n22;

    float2 r01, r23, r45;
    r01.x = fmaf(d2v, p00, fmaf(d1v, m00, d0v));
    r01.y = fmaf(d2v, p01, d1v * c01);
    r23.x = fmaf(d2v, p02, d1v * c02);
    r23.y = fmaf(d2v, p11, fmaf(d1v, m11, d0v));
    r45.x = fmaf(d2v, p12, d1v * c12);
    r45.y = fmaf(d2v, p22, fmaf(d1v, m22, d0v));

    float2* ob = reinterpret_cast<float2*>(outp);
    ob[0] = r01;
    ob[1] = r23;
    ob[2] = r45;
}

__global__ __launch_bounds__(32, 7) void spd_kernel(const float* __restrict__ X,
                                                    const float* __restrict__ W1,
                                                    const float* __restrict__ W2,
                                                    const float* __restrict__ W3,
                                                    float* __restrict__ out,
                                                    int B, int nmc) {
    extern __shared__ __align__(16) float dsm[];           // DEPTH x 2592 floats
    __shared__ __align__(8) unsigned long long mbar_s[DEPTH];
    __shared__ float sW[27];

    const int lane = threadIdx.x;

    // Wc = W1 @ W2 @ W3 (9x3); tiny, L2-resident across blocks
    if (lane < 27) {
        int i = lane / 3, cc = lane % 3;
        float s = 0.f;
        #pragma unroll
        for (int m5 = 0; m5 < 5; ++m5) {
            float t = 0.f;
            #pragma unroll
            for (int k = 0; k < 7; ++k)
                t = fmaf(__ldg(W1 + i * 7 + k), __ldg(W2 + k * 5 + m5), t);
            s = fmaf(t, __ldg(W3 + m5 * 3 + cc), s);
        }
        sW[lane] = s;
    }

    const unsigned mb0 = s2u(&mbar_s[0]);
    const unsigned mb1 = s2u(&mbar_s[1]);
    const unsigned mb2 = s2u(&mbar_s[2]);
    if (lane == 0) {
        mbar_init(mb0, 1);
        mbar_init(mb1, 1);
        mbar_init(mb2, 1);
    }
    __syncwarp();   // mbarrier init + sW visible warp-wide

    unsigned ph0 = 0, ph1 = 0, ph2 = 0;
    const unsigned sb0 = s2u(dsm);
    const unsigned sb1 = sb0 + MCB;
    const unsigned sb2 = sb0 + 2 * MCB;
    const float* d0 = dsm;
    const float* d1 = dsm + MCF;
    const float* d2 = dsm + 2 * MCF;

    const int c0 = blockIdx.x;
    const int stride = gridDim.x;

    // prologue: fill slots 0 and 1 (prefetch distance 2)
    if (lane == 0) {
        if (c0 < nmc && (c0 + 1) * MC <= B)
            issue_bulk(sb0, X + (size_t)c0 * MCF, MCB, mb0);
        int cp = c0 + stride;
        if (cp < nmc && (cp + 1) * MC <= B)
            issue_bulk(sb1, X + (size_t)cp * MCF, MCB, mb1);
    }

    for (int c = c0; c < nmc; c += 3 * stride) {
        // ---- slot 0: chunk c ----
        {
            int pn = c + 2 * stride;     // prefetch into slot 2
            if (pn < nmc && (pn + 1) * MC <= B && lane == 0)
                issue_bulk(sb2, X + (size_t)pn * MCF, MCB, mb2);
            int bstart = c * MC;
            if (bstart + MC <= B) {
                mbar_wait(mb0, ph0); ph0 ^= 1;
                compute_store(d0 + lane * 81, sW, out + ((size_t)bstart + lane) * 6);
            } else if (bstart + lane < B) {
                float xl[81];
                const float* g = X + ((size_t)bstart + lane) * 81;
                #pragma unroll
                for (int e = 0; e < 81; ++e) xl[e] = __ldg(g + e);
                compute_store(xl, sW, out + ((size_t)bstart + lane) * 6);
            }
        }
        // ---- slot 1: chunk c + stride ----
        int c1 = c + stride;
        if (c1 < nmc) {
            int pn = c1 + 2 * stride;    // prefetch into slot 0
            if (pn < nmc && (pn + 1) * MC <= B && lane == 0)
                issue_bulk(sb0, X + (size_t)pn * MCF, MCB, mb0);
            int bstart = c1 * MC;
            if (bstart + MC <= B) {
                mbar_wait(mb1, ph1); ph1 ^= 1;
                compute_store(d1 + lane * 81, sW, out + ((size_t)bstart + lane) * 6);
            } else if (bstart + lane < B) {
                float xl[81];
                const float* g = X + ((size_t)bstart + lane) * 81;
                #pragma unroll
                for (int e = 0; e < 81; ++e) xl[e] = __ldg(g + e);
                compute_store(xl, sW, out + ((size_t)bstart + lane) * 6);
            }
        }
        // ---- slot 2: chunk c + 2*stride ----
        int c2 = c + 2 * stride;
        if (c2 < nmc) {
            int pn = c2 + 2 * stride;    // prefetch into slot 1
            if (pn < nmc && (pn + 1) * MC <= B && lane == 0)
                issue_bulk(sb1, X + (size_t)pn * MCF, MCB, mb1);
            int bstart = c2 * MC;
            if (bstart + MC <= B) {
                mbar_wait(mb2, ph2); ph2 ^= 1;
                compute_store(d2 + lane * 81, sW, out + ((size_t)bstart + lane) * 6);
            } else if (bstart + lane < B) {
                float xl[81];
                const float* g = X + ((size_t)bstart + lane) * 81;
                #pragma unroll
                for (int e = 0; e < 81; ++e) xl[e] = __ldg(g + e);
                compute_store(xl, sW, out + ((size_t)bstart + lane) * 6);
            }
        }
    }
}

extern "C" void kernel_launch(void* const* d_in, const int* in_sizes, int n_in,
                              void* d_out, int out_size) {
    const float* X  = (const float*)d_in[0];
    const float* W1 = (const float*)d_in[1];
    const float* W2 = (const float*)d_in[2];
    const float* W3 = (const float*)d_in[3];
    float* out = (float*)d_out;

    int B = in_sizes[0] / 81;
    int nmc = (B + MC - 1) / MC;

    int sms = 148;
    cudaDeviceGetAttribute(&sms, cudaDevAttrMultiProcessorCount, 0);
    int grid = 7 * sms;              // 7 one-warp blocks/SM (31.1 KB smem each)
    if (grid > nmc) grid = nmc;

    spd_kernel<<<grid, 32, SMEM_DYN>>>(X, W1, W2, W3, out, B, nmc);
}